// round 11
// baseline (speedup 1.0000x reference)
#include <cuda_runtime.h>

#define NB   64
#define SEQL 4096
#define DIM  64
#define NEG  (-10000.0f)

#define PQ 68            // pitch Qs / Ps (mult of 4: 16B aligned; 1-row stride = 16B-group step)
#define PK 68            // pitch Ks
#define PVV 64

#define QS_OFF 0
#define KS_OFF (64*PQ)
#define VS_OFF (KS_OFF + 64*PK)
#define PS_OFF (VS_OFF + 64*PVV)
#define SMEM_FLOATS (PS_OFF + 64*PQ)
#define SMEM_BYTES  (SMEM_FLOATS * 4)

typedef unsigned long long u64;

__device__ __forceinline__ u64 ffma2(u64 a, u64 b, u64 c) {
    u64 d;
    asm("fma.rn.f32x2 %0, %1, %2, %3;" : "=l"(d) : "l"(a), "l"(b), "l"(c));
    return d;
}
__device__ __forceinline__ u64 fmul2(u64 a, u64 b) {
    u64 d;
    asm("mul.rn.f32x2 %0, %1, %2;" : "=l"(d) : "l"(a), "l"(b));
    return d;
}
__device__ __forceinline__ u64 splat2(float x) {
    u64 d; unsigned int u = __float_as_uint(x);
    asm("mov.b64 %0, {%1, %1};" : "=l"(d) : "r"(u));
    return d;
}
__device__ __forceinline__ float2 unpack2(u64 a) {
    unsigned int lo, hi;
    asm("mov.b64 {%0, %1}, %2;" : "=r"(lo), "=r"(hi) : "l"(a));
    return make_float2(__uint_as_float(lo), __uint_as_float(hi));
}

__global__ __launch_bounds__(128, 3)
void bb_attn_kernel(const float*  __restrict__ Q,
                    const float*  __restrict__ K,
                    const float*  __restrict__ V,
                    const int*    __restrict__ rand_attn,
                    const float*  __restrict__ from_mask,
                    const float*  __restrict__ to_mask,
                    const float*  __restrict__ rand_mask,
                    const float*  __restrict__ band_mask,
                    float*        __restrict__ out)
{
    extern __shared__ float sm[];
    float* Qs = sm + QS_OFF;
    float* Ks = sm + KS_OFF;
    float* Vs = sm + VS_OFF;
    float* Ps = sm + PS_OFF;

    // heavy-first remap: full-attention blocks first
    int i, bh;
    {
        int bid = blockIdx.x;
        if (bid < 64) { bh = bid >> 1; i = (bid & 1) ? (NB - 1) : 0; }
        else          { int x = bid - 64; bh = x / 62; i = 1 + (x - bh * 62); }
    }
    const int b   = bh >> 4;
    const int tid = threadIdx.x;
    const int jg  = tid & 7;
    const int qg  = tid >> 3;         // 0..15; thread owns q-rows qg + 16*r, r=0..3

    // ---- load Q (pre-scaled by 1/8, exact) ----
    const float* Qg = Q + ((size_t)bh * SEQL + (size_t)i * 64) * DIM;
    for (int f = tid; f < 1024; f += 128) {
        int row = f >> 4, c4 = (f & 15) << 2;
        float4 t4 = __ldg((const float4*)(Qg + row * DIM + c4));
        t4.x *= 0.125f; t4.y *= 0.125f; t4.z *= 0.125f; t4.w *= 0.125f;
        *(float4*)(Qs + row * PQ + c4) = t4;
    }

    // ---- key-block list ----
    const bool full = (i == 0 || i == NB - 1);
    int nt;
    int kbl[8], mtl[8], mpl[8];
    if (full) {
        nt = NB;
    } else {
        const int* ra = rand_attn + ((size_t)bh * (NB - 2) + (i - 1)) * 3;
        int r0 = __ldg(ra + 0), r1 = __ldg(ra + 1), r2 = __ldg(ra + 2);
        if (i == 1) {
            kbl[0]=0; kbl[1]=1; kbl[2]=2; kbl[3]=NB-1;
            mtl[0]=mtl[1]=mtl[2]=mtl[3]=0; mpl[0]=mpl[1]=mpl[2]=mpl[3]=0;
            kbl[4]=r0; kbl[5]=r1; kbl[6]=r2;
            mtl[4]=mtl[5]=mtl[6]=2; mpl[4]=0; mpl[5]=1; mpl[6]=2;
            nt = 7;
        } else if (i == NB - 2) {
            kbl[0]=0; kbl[1]=NB-3; kbl[2]=NB-2; kbl[3]=NB-1;
            mtl[0]=mtl[1]=mtl[2]=mtl[3]=0; mpl[0]=mpl[1]=mpl[2]=mpl[3]=0;
            kbl[4]=r0; kbl[5]=r1; kbl[6]=r2;
            mtl[4]=mtl[5]=mtl[6]=2; mpl[4]=0; mpl[5]=1; mpl[6]=2;
            nt = 7;
        } else {
            kbl[0]=0;    mtl[0]=0; mpl[0]=0;
            kbl[1]=i-1;  mtl[1]=1; mpl[1]=0;
            kbl[2]=i;    mtl[2]=1; mpl[2]=1;
            kbl[3]=i+1;  mtl[3]=1; mpl[3]=2;
            kbl[4]=r0;   mtl[4]=2; mpl[4]=0;
            kbl[5]=r1;   mtl[5]=2; mpl[5]=1;
            kbl[6]=r2;   mtl[6]=2; mpl[6]=2;
            kbl[7]=NB-1; mtl[7]=0; mpl[7]=0;
            nt = 8;
        }
    }

    // ---- packed accumulators: dims [4jg,4jg+4) and [32+4jg,+4) as f32x2 pairs ----
    u64 acc2[4][4];
    float mrow[4], lrow[4];
    #pragma unroll
    for (int r = 0; r < 4; r++) {
        mrow[r] = -1e30f; lrow[r] = 0.0f;
        #pragma unroll
        for (int p = 0; p < 4; p++) acc2[r][p] = 0ull;
    }

    for (int t = 0; t < nt; t++) {
        int kb, mt, mp;
        if (full) { kb = t; mt = 0; mp = 0; }
        else      { kb = kbl[t]; mt = mtl[t]; mp = mpl[t]; }

        __syncthreads();

        // ---- load K, V tile ----
        const float* Kg = K + ((size_t)bh * SEQL + (size_t)kb * 64) * DIM;
        const float* Vg = V + ((size_t)bh * SEQL + (size_t)kb * 64) * DIM;
        for (int f = tid; f < 1024; f += 128) {
            int row = f >> 4, c4 = (f & 15) << 2;
            float4 kk = __ldg((const float4*)(Kg + row * DIM + c4));
            *(float4*)(Ks + row * PK + c4) = kk;
            float4 vv = __ldg((const float4*)(Vg + row * DIM + c4));
            *(float4*)(Vs + row * PVV + c4) = vv;
        }
        __syncthreads();

        // ---- QK^T with f32x2, paired over d; two column-halves to cap regs ----
        float s[4][8];
        #pragma unroll 1
        for (int h = 0; h < 2; h++) {
            u64 s2[4][4];
            #pragma unroll
            for (int r = 0; r < 4; r++)
                #pragma unroll
                for (int c = 0; c < 4; c++) s2[r][c] = 0ull;

            #pragma unroll 4
            for (int d4 = 0; d4 < 16; d4++) {
                ulonglong2 qv[4], kv[4];
                #pragma unroll
                for (int r = 0; r < 4; r++)
                    qv[r] = *(const ulonglong2*)(const void*)(Qs + (qg + (r << 4)) * PQ + (d4 << 2));
                #pragma unroll
                for (int c = 0; c < 4; c++)
                    kv[c] = *(const ulonglong2*)(const void*)(Ks + (jg + ((h * 4 + c) << 3)) * PK + (d4 << 2));
                #pragma unroll
                for (int r = 0; r < 4; r++)
                    #pragma unroll
                    for (int c = 0; c < 4; c++) {
                        s2[r][c] = ffma2(qv[r].x, kv[c].x, s2[r][c]);
                        s2[r][c] = ffma2(qv[r].y, kv[c].y, s2[r][c]);
                    }
            }
            #pragma unroll
            for (int r = 0; r < 4; r++)
                #pragma unroll
                for (int c = 0; c < 4; c++) {
                    float2 u = unpack2(s2[r][c]);
                    s[r][h * 4 + c] = u.x + u.y;
                }
        }

        // ---- mask (q-row for slot r is qg + 16r) ----
        if (mt == 0) {
            const float* tmp = to_mask + (size_t)b * SEQL + (size_t)kb * 64 + jg;
            float tadd[8];
            #pragma unroll
            for (int c = 0; c < 8; c++)
                tadd[c] = (1.0f - __ldg(tmp + (c << 3))) * NEG;
            #pragma unroll
            for (int r = 0; r < 4; r++)
                #pragma unroll
                for (int c = 0; c < 8; c++)
                    s[r][c] += tadd[c];
        } else if (mt == 1) {
            const float* bm = band_mask
                + (((size_t)b * (NB - 4) + (i - 2)) * 64) * 192 + mp * 64 + jg;
            #pragma unroll
            for (int r = 0; r < 4; r++) {
                const float* bmr = bm + (size_t)(qg + (r << 4)) * 192;
                #pragma unroll
                for (int c = 0; c < 8; c++)
                    s[r][c] += (1.0f - __ldg(bmr + (c << 3))) * NEG;
            }
        } else {
            const float* rm = rand_mask
                + (((size_t)bh * (NB - 2) + (i - 1)) * 64) * 192 + mp * 64 + jg;
            #pragma unroll
            for (int r = 0; r < 4; r++) {
                const float* rmr = rm + (size_t)(qg + (r << 4)) * 192;
                #pragma unroll
                for (int c = 0; c < 8; c++)
                    s[r][c] += (1.0f - __ldg(rmr + (c << 3))) * NEG;
            }
        }

        // ---- online softmax (8-lane row groups) ----
        #pragma unroll
        for (int r = 0; r < 4; r++) {
            float mx = s[r][0];
            #pragma unroll
            for (int c = 1; c < 8; c++) mx = fmaxf(mx, s[r][c]);
            mx = fmaxf(mx, __shfl_xor_sync(0xffffffffu, mx, 1));
            mx = fmaxf(mx, __shfl_xor_sync(0xffffffffu, mx, 2));
            mx = fmaxf(mx, __shfl_xor_sync(0xffffffffu, mx, 4));
            float mnew = fmaxf(mrow[r], mx);
            float corr = __expf(mrow[r] - mnew);
            float ls = 0.0f;
            #pragma unroll
            for (int c = 0; c < 8; c++) {
                float p = __expf(s[r][c] - mnew);
                s[r][c] = p;
                ls += p;
            }
            ls += __shfl_xor_sync(0xffffffffu, ls, 1);
            ls += __shfl_xor_sync(0xffffffffu, ls, 2);
            ls += __shfl_xor_sync(0xffffffffu, ls, 4);
            lrow[r] = lrow[r] * corr + ls;
            mrow[r] = mnew;
            u64 corr2 = splat2(corr);
            #pragma unroll
            for (int p = 0; p < 4; p++) acc2[r][p] = fmul2(acc2[r][p], corr2);
            #pragma unroll
            for (int c = 0; c < 8; c++)
                Ps[(qg + (r << 4)) * PQ + jg + (c << 3)] = s[r][c];
        }
        __syncthreads();

        // ---- PV with f32x2, paired over output dims ----
        #pragma unroll 4
        for (int j4 = 0; j4 < 16; j4++) {
            float4 pv[4];
            #pragma unroll
            for (int r = 0; r < 4; r++)
                pv[r] = *(const float4*)(Ps + (qg + (r << 4)) * PQ + (j4 << 2));
            ulonglong2 va[4], vb[4];
            #pragma unroll
            for (int jj = 0; jj < 4; jj++) {
                const float* vrow = Vs + ((j4 << 2) + jj) * PVV;
                va[jj] = *(const ulonglong2*)(const void*)(vrow + (jg << 2));
                vb[jj] = *(const ulonglong2*)(const void*)(vrow + 32 + (jg << 2));
            }
            #pragma unroll
            for (int r = 0; r < 4; r++) {
                float pr[4] = { pv[r].x, pv[r].y, pv[r].z, pv[r].w };
                #pragma unroll
                for (int jj = 0; jj < 4; jj++) {
                    u64 p2 = splat2(pr[jj]);
                    acc2[r][0] = ffma2(p2, va[jj].x, acc2[r][0]);
                    acc2[r][1] = ffma2(p2, va[jj].y, acc2[r][1]);
                    acc2[r][2] = ffma2(p2, vb[jj].x, acc2[r][2]);
                    acc2[r][3] = ffma2(p2, vb[jj].y, acc2[r][3]);
                }
            }
        }
    }

    // ---- epilogue (q-row for slot r is qg + 16r) ----
    float* og = out + ((size_t)bh * SEQL + (size_t)i * 64) * DIM;
    #pragma unroll
    for (int r = 0; r < 4; r++) {
        int qrow = qg + (r << 4);
        float fm = __ldg(from_mask + (size_t)b * SEQL + (size_t)i * 64 + qrow);
        float inv = fm / lrow[r];
        float2 a0 = unpack2(acc2[r][0]);
        float2 a1 = unpack2(acc2[r][1]);
        float2 b0 = unpack2(acc2[r][2]);
        float2 b1 = unpack2(acc2[r][3]);
        float4 oa = make_float4(a0.x*inv, a0.y*inv, a1.x*inv, a1.y*inv);
        float4 ob = make_float4(b0.x*inv, b0.y*inv, b1.x*inv, b1.y*inv);
        *(float4*)(og + qrow * DIM + (jg << 2))      = oa;
        *(float4*)(og + qrow * DIM + 32 + (jg << 2)) = ob;
    }
}

extern "C" void kernel_launch(void* const* d_in, const int* in_sizes, int n_in,
                              void* d_out, int out_size)
{
    const float* Q  = (const float*)d_in[0];
    const float* K  = (const float*)d_in[1];
    const float* V  = (const float*)d_in[2];
    const int*   RA = (const int*)  d_in[3];
    const float* FM = (const float*)d_in[4];
    const float* TM = (const float*)d_in[5];
    const float* RM = (const float*)d_in[6];
    const float* BM = (const float*)d_in[7];
    float* O = (float*)d_out;

    cudaFuncSetAttribute(bb_attn_kernel,
                         cudaFuncAttributeMaxDynamicSharedMemorySize, SMEM_BYTES);

    dim3 grid(2 * 16 * NB);
    bb_attn_kernel<<<grid, 128, SMEM_BYTES>>>(Q, K, V, RA, FM, TM, RM, BM, O);
}